// round 9
// baseline (speedup 1.0000x reference)
#include <cuda_runtime.h>
#include <stdint.h>
#include <math.h>

// ---------------------------------------------------------------------------
// out[b,o] = min_i ( x[b,i] + mask[o,i] ),  B=IN=OUT=512,  x in [0,1)
// mask in {0,1}  =>  out[b,o] = min over SELECTED i of x[b,i]  (sparse min).
// Selection = JAX threefry bernoulli (partitionable variant, validated R2-R8).
// ---------------------------------------------------------------------------

#define B_DIM   512
#define IN_DIM  512
#define OUT_DIM 512
#define OW      (OUT_DIM / 32)      // 16 o-words

// column-major selection bitmask: bit o%32 of g_selC[(o>>5)*512 + i]
__device__ uint32_t g_selC[OW * IN_DIM];
__device__ uint2    g_top[B_DIM * 64];   // (idx, exact valbits), sorted per b-row

// ---------------- Threefry-2x32 (constexpr) --------------------------------
struct TF2 { uint32_t a, b; };

__host__ __device__ constexpr uint32_t rotl32(uint32_t v, int r) {
    return (v << r) | (v >> (32 - r));
}

__host__ __device__ constexpr TF2 tf2x32(uint32_t k0, uint32_t k1,
                                         uint32_t x0, uint32_t x1) {
    uint32_t k2 = k0 ^ k1 ^ 0x1BD11BDAu;
    x0 += k0; x1 += k1;
    x0 += x1; x1 = rotl32(x1, 13) ^ x0;
    x0 += x1; x1 = rotl32(x1, 15) ^ x0;
    x0 += x1; x1 = rotl32(x1, 26) ^ x0;
    x0 += x1; x1 = rotl32(x1,  6) ^ x0;
    x0 += k1; x1 += k2 + 1u;
    x0 += x1; x1 = rotl32(x1, 17) ^ x0;
    x0 += x1; x1 = rotl32(x1, 29) ^ x0;
    x0 += x1; x1 = rotl32(x1, 16) ^ x0;
    x0 += x1; x1 = rotl32(x1, 24) ^ x0;
    x0 += k2; x1 += k0 + 2u;
    x0 += x1; x1 = rotl32(x1, 13) ^ x0;
    x0 += x1; x1 = rotl32(x1, 15) ^ x0;
    x0 += x1; x1 = rotl32(x1, 26) ^ x0;
    x0 += x1; x1 = rotl32(x1,  6) ^ x0;
    x0 += k0; x1 += k1 + 3u;
    x0 += x1; x1 = rotl32(x1, 17) ^ x0;
    x0 += x1; x1 = rotl32(x1, 29) ^ x0;
    x0 += x1; x1 = rotl32(x1, 16) ^ x0;
    x0 += x1; x1 = rotl32(x1, 24) ^ x0;
    x0 += k1; x1 += k2 + 4u;
    x0 += x1; x1 = rotl32(x1, 13) ^ x0;
    x0 += x1; x1 = rotl32(x1, 15) ^ x0;
    x0 += x1; x1 = rotl32(x1, 26) ^ x0;
    x0 += x1; x1 = rotl32(x1,  6) ^ x0;
    x0 += k2; x1 += k0 + 5u;
    return TF2{x0, x1};
}

constexpr TF2 KB = tf2x32(0u, 42u, 0u, 0u);   // k_bern (foldlike split of key 42)

// ---------------- bernoulli decision (validated) -----------------------------
__device__ __forceinline__ bool edge_selected(const float2 w, uint32_t n) {
    TF2 r = tf2x32(KB.a, KB.b, 0u, n);
    uint32_t bits = r.a ^ r.b;
    float u = __uint_as_float((bits >> 9) | 0x3F800000u) - 1.0f;
    float t = u * (1.0f + __expf(w.x - w.y));
    if (t < 1.0f - 1e-5f) return true;
    if (t > 1.0f + 1e-5f) return false;
    double e = exp((double)w.x - (double)w.y);       // boundary: exact fp64
    return ((double)u) * (1.0 + e) < 1.0;
}

// ---------------- bitonic helpers (2 elems/thread: e0=2t, e1=2t+1) ----------
#define BSWAP(A, PA, KEEPMIN) ((KEEPMIN) ? umin((A),(PA)) : umax((A),(PA)))

#define STAGE_J1(K) {                                                         \
    bool dir = (((2*t) & (K)) == 0);                                          \
    uint32_t lo = umin(a, b), hi = umax(a, b);                                \
    a = dir ? lo : hi; b = dir ? hi : lo; }

#define STAGE_SHFL(J, K) {                                                    \
    uint32_t pa = __shfl_xor_sync(0xFFFFFFFFu, a, (J) >> 1);                  \
    uint32_t pb = __shfl_xor_sync(0xFFFFFFFFu, b, (J) >> 1);                  \
    bool dir = (((2*t) & (K)) == 0);                                          \
    bool lower = ((t & ((J) >> 1)) == 0);                                     \
    bool km = (dir == lower);                                                 \
    a = BSWAP(a, pa, km); b = BSWAP(b, pb, km); }

#define STAGE_SMEM(J, K) {                                                    \
    __syncthreads();                                                          \
    sk[2*t] = a; sk[2*t+1] = b;                                               \
    __syncthreads();                                                          \
    uint32_t pa = sk[(2*t) ^ (J)];                                            \
    uint32_t pb = sk[(2*t+1) ^ (J)];                                          \
    bool dir = (((2*t) & (K)) == 0);                                          \
    bool lower = (((2*t) & (J)) == 0);                                        \
    bool km = (dir == lower);                                                 \
    a = BSWAP(a, pa, km); b = BSWAP(b, pb, km); }

#define TAIL32(K) STAGE_SHFL(32,K) STAGE_SHFL(16,K) STAGE_SHFL(8,K) \
                  STAGE_SHFL(4,K)  STAGE_SHFL(2,K)  STAGE_J1(K)

// ---------------- 1) combined mask + sort (block-divergent grid) ------------
// blocks [0,512): sort b-row.  blocks [512,768): mask 32o x 32i tile, ILP=4.
__global__ __launch_bounds__(256) void prep_kernel(
    const float* __restrict__ x, const float* __restrict__ pw) {
    __shared__ uint32_t sk[512];
    __shared__ float s_xv[512];
    const int t = threadIdx.x;

    if (blockIdx.x >= 512) {
        // ---- mask tile: lane = o (ballot dim), warp+k = i ; 4 chains/thread
        const uint32_t m  = blockIdx.x - 512;       // 0..255
        const uint32_t ob = (m & 15u) * 32u;        // o-block
        const uint32_t ib = (m >> 4) * 32u;         // i-block
        const uint32_t l  = t & 31u;
        const uint32_t w  = (uint32_t)t >> 5;
        const uint32_t o  = ob + l;
        const uint32_t ow = ob >> 5;

        uint32_t iidx[4];
        bool s[4];
#pragma unroll
        for (int k = 0; k < 4; ++k) {
            iidx[k] = ib + w + 8u * k;
            uint32_t n = o * 512u + iidx[k];
            float2 wt = reinterpret_cast<const float2*>(pw)[n];
            s[k] = edge_selected(wt, n);
        }
#pragma unroll
        for (int k = 0; k < 4; ++k) {
            uint32_t word = __ballot_sync(0xFFFFFFFFu, s[k]);
            if (l == 0) g_selC[ow * 512u + iidx[k]] = word;   // column-major
        }
        return;
    }

    // ---- sort half: bitonic on 512 keys, 2 per thread in registers
    const int row = blockIdx.x;
    float2 xv = reinterpret_cast<const float2*>(x + row * IN_DIM)[t];
    s_xv[2*t]   = xv.x;                        // exact values for final emit
    s_xv[2*t+1] = xv.y;
    // key = (valbits>>7)<<9 | idx  (monotone in value, 128-ulp ties)
    uint32_t a = ((__float_as_uint(xv.x) >> 7) << 9) | (uint32_t)(2*t);
    uint32_t b = ((__float_as_uint(xv.y) >> 7) << 9) | (uint32_t)(2*t+1);

    STAGE_J1(2)
    STAGE_SHFL(2,4)  STAGE_J1(4)
    STAGE_SHFL(4,8)  STAGE_SHFL(2,8)  STAGE_J1(8)
    STAGE_SHFL(8,16) STAGE_SHFL(4,16) STAGE_SHFL(2,16) STAGE_J1(16)
    STAGE_SHFL(16,32) STAGE_SHFL(8,32) STAGE_SHFL(4,32) STAGE_SHFL(2,32) STAGE_J1(32)
    STAGE_SHFL(32,64) STAGE_SHFL(16,64) STAGE_SHFL(8,64) STAGE_SHFL(4,64)
    STAGE_SHFL(2,64)  STAGE_J1(64)
    STAGE_SMEM(64,128)  TAIL32(128)
    STAGE_SMEM(128,256) STAGE_SMEM(64,256) TAIL32(256)
    STAGE_SMEM(256,512) STAGE_SMEM(128,512) STAGE_SMEM(64,512) TAIL32(512)

    if (t < 32) {                      // threads 0..31 hold sorted elems 0..63
        uint32_t ia = a & 511u, ib2 = b & 511u;
        g_top[row * 64 + 2*t]     = make_uint2(ia, __float_as_uint(s_xv[ia]));
        g_top[row * 64 + 2*t + 1] = make_uint2(ib2, __float_as_uint(s_xv[ib2]));
    }
}

// ---------------- 2) gather: one WARP per (b, o-word), ballot-transpose -----
// lane l probes candidate l for all 32 o's at once; 32 ballots transpose the
// 32x32 candidate-hit matrix so lane o gets first-hit j via ffs.
__global__ __launch_bounds__(512) void gather_kernel(
    const float* __restrict__ x, float* __restrict__ out) {
    const int b    = blockIdx.x;
    const uint32_t ow = (uint32_t)threadIdx.x >> 5;   // warp -> o-word
    const int lane = threadIdx.x & 31;

    // candidate lane: (idx, exact value)
    uint2 kv = g_top[b * 64 + lane];                  // coalesced
    uint32_t m = g_selC[ow * 512u + kv.x];            // parallel scattered, L2-hot
    float val = __uint_as_float(kv.y);

    // transpose: lane o collects bit-l = hit(candidate l, output o)
    uint32_t myw = 0;
#pragma unroll
    for (int o = 0; o < 32; ++o) {
        uint32_t bal = __ballot_sync(0xFFFFFFFFu, (m >> o) & 1u);
        if (lane == o) myw = bal;
    }

    bool ok = (myw != 0);
    int j = __ffs(myw) - 1;
    float res = __shfl_sync(0xFFFFFFFFu, val, ok ? j : 0);

    if (!__all_sync(0xFFFFFFFFu, ok)) {               // P ~ 1.3e-3 per warp
        uint2 kv2 = g_top[b * 64 + 32 + lane];
        uint32_t m2 = g_selC[ow * 512u + kv2.x];
        float val2 = __uint_as_float(kv2.y);
        uint32_t myw2 = 0;
#pragma unroll
        for (int o = 0; o < 32; ++o) {
            uint32_t bal = __ballot_sync(0xFFFFFFFFu, (m2 >> o) & 1u);
            if (lane == o) myw2 = bal;
        }
        int j2 = __ffs(myw2) - 1;
        float r2 = __shfl_sync(0xFFFFFFFFu, val2, myw2 ? j2 : 0);
        if (!ok && myw2) { res = r2; ok = true; }

        if (!ok) {                                    // P ~ 1e-9: exact dense
            float best = INFINITY, ball2 = INFINITY;
            const float* xr = x + b * IN_DIM;
            for (int i = 0; i < IN_DIM; ++i) {
                float v = xr[i];
                ball2 = fminf(ball2, v);
                if ((g_selC[ow * 512u + i] >> lane) & 1u) best = fminf(best, v);
            }
            res = isinf(best) ? ball2 + 1.0f : best;  // zero-selected: impossible
        }
    }

    out[b * OUT_DIM + ow * 32u + lane] = res;         // coalesced
}

// ---------------------------------------------------------------------------
extern "C" void kernel_launch(void* const* d_in, const int* in_sizes, int n_in,
                              void* d_out, int out_size) {
    const float* x  = (const float*)d_in[0];   // [512, 512]
    const float* pw = (const float*)d_in[1];   // [512, 512, 2]
    float* out      = (float*)d_out;           // [512, 512]

    prep_kernel<<<768, 256>>>(x, pw);
    gather_kernel<<<B_DIM, 512>>>(x, out);
}

// round 10
// speedup vs baseline: 1.4060x; 1.4060x over previous
#include <cuda_runtime.h>
#include <stdint.h>
#include <math.h>

// ---------------------------------------------------------------------------
// out[b,o] = min_i ( x[b,i] + mask[o,i] ),  B=IN=OUT=512,  x in [0,1)
// mask in {0,1}  =>  out[b,o] = min over SELECTED i of x[b,i]  (sparse min).
// Selection = JAX threefry bernoulli (partitionable variant, validated R2-R9).
// ---------------------------------------------------------------------------

#define B_DIM   512
#define IN_DIM  512
#define OUT_DIM 512
#define OW      (OUT_DIM / 32)      // 16 o-words

// column-major selection bitmask: bit o%32 of g_selC[(o>>5)*512 + i]
__device__ uint32_t g_selC[OW * IN_DIM];
__device__ uint2    g_top[B_DIM * 64];   // (idx, exact valbits), sorted per b-row

// ---------------- Threefry-2x32 (constexpr) --------------------------------
struct TF2 { uint32_t a, b; };

__host__ __device__ constexpr uint32_t rotl32(uint32_t v, int r) {
    return (v << r) | (v >> (32 - r));
}

__host__ __device__ constexpr TF2 tf2x32(uint32_t k0, uint32_t k1,
                                         uint32_t x0, uint32_t x1) {
    uint32_t k2 = k0 ^ k1 ^ 0x1BD11BDAu;
    x0 += k0; x1 += k1;
    x0 += x1; x1 = rotl32(x1, 13) ^ x0;
    x0 += x1; x1 = rotl32(x1, 15) ^ x0;
    x0 += x1; x1 = rotl32(x1, 26) ^ x0;
    x0 += x1; x1 = rotl32(x1,  6) ^ x0;
    x0 += k1; x1 += k2 + 1u;
    x0 += x1; x1 = rotl32(x1, 17) ^ x0;
    x0 += x1; x1 = rotl32(x1, 29) ^ x0;
    x0 += x1; x1 = rotl32(x1, 16) ^ x0;
    x0 += x1; x1 = rotl32(x1, 24) ^ x0;
    x0 += k2; x1 += k0 + 2u;
    x0 += x1; x1 = rotl32(x1, 13) ^ x0;
    x0 += x1; x1 = rotl32(x1, 15) ^ x0;
    x0 += x1; x1 = rotl32(x1, 26) ^ x0;
    x0 += x1; x1 = rotl32(x1,  6) ^ x0;
    x0 += k0; x1 += k1 + 3u;
    x0 += x1; x1 = rotl32(x1, 17) ^ x0;
    x0 += x1; x1 = rotl32(x1, 29) ^ x0;
    x0 += x1; x1 = rotl32(x1, 16) ^ x0;
    x0 += x1; x1 = rotl32(x1, 24) ^ x0;
    x0 += k1; x1 += k2 + 4u;
    x0 += x1; x1 = rotl32(x1, 13) ^ x0;
    x0 += x1; x1 = rotl32(x1, 15) ^ x0;
    x0 += x1; x1 = rotl32(x1, 26) ^ x0;
    x0 += x1; x1 = rotl32(x1,  6) ^ x0;
    x0 += k2; x1 += k0 + 5u;
    return TF2{x0, x1};
}

constexpr TF2 KB = tf2x32(0u, 42u, 0u, 0u);   // k_bern (foldlike split of key 42)

// ---------------- bernoulli decision (validated) -----------------------------
__device__ __forceinline__ bool edge_selected(const float2 w, uint32_t n) {
    TF2 r = tf2x32(KB.a, KB.b, 0u, n);
    uint32_t bits = r.a ^ r.b;
    float u = __uint_as_float((bits >> 9) | 0x3F800000u) - 1.0f;
    float t = u * (1.0f + __expf(w.x - w.y));
    if (t < 1.0f - 1e-5f) return true;
    if (t > 1.0f + 1e-5f) return false;
    double e = exp((double)w.x - (double)w.y);       // boundary: exact fp64
    return ((double)u) * (1.0 + e) < 1.0;
}

// ---------------- bitonic helpers (2 elems/thread: e0=2t, e1=2t+1) ----------
#define BSWAP(A, PA, KEEPMIN) ((KEEPMIN) ? umin((A),(PA)) : umax((A),(PA)))

#define STAGE_J1(K) {                                                         \
    bool dir = (((2*t) & (K)) == 0);                                          \
    uint32_t lo = umin(a, b), hi = umax(a, b);                                \
    a = dir ? lo : hi; b = dir ? hi : lo; }

#define STAGE_SHFL(J, K) {                                                    \
    uint32_t pa = __shfl_xor_sync(0xFFFFFFFFu, a, (J) >> 1);                  \
    uint32_t pb = __shfl_xor_sync(0xFFFFFFFFu, b, (J) >> 1);                  \
    bool dir = (((2*t) & (K)) == 0);                                          \
    bool lower = ((t & ((J) >> 1)) == 0);                                     \
    bool km = (dir == lower);                                                 \
    a = BSWAP(a, pa, km); b = BSWAP(b, pb, km); }

#define STAGE_SMEM(J, K) {                                                    \
    __syncthreads();                                                          \
    sk[2*t] = a; sk[2*t+1] = b;                                               \
    __syncthreads();                                                          \
    uint32_t pa = sk[(2*t) ^ (J)];                                            \
    uint32_t pb = sk[(2*t+1) ^ (J)];                                          \
    bool dir = (((2*t) & (K)) == 0);                                          \
    bool lower = (((2*t) & (J)) == 0);                                        \
    bool km = (dir == lower);                                                 \
    a = BSWAP(a, pa, km); b = BSWAP(b, pb, km); }

#define TAIL32(K) STAGE_SHFL(32,K) STAGE_SHFL(16,K) STAGE_SHFL(8,K) \
                  STAGE_SHFL(4,K)  STAGE_SHFL(2,K)  STAGE_J1(K)

// ---------------- 1) combined mask + sort (block-divergent grid) ------------
// blocks [0,512): sort b-row.  blocks [512,768): mask 32o x 32i tile, ILP=4.
__global__ __launch_bounds__(256) void prep_kernel(
    const float* __restrict__ x, const float* __restrict__ pw) {
    __shared__ uint32_t sk[512];
    __shared__ float s_xv[512];
    const int t = threadIdx.x;

    if (blockIdx.x >= 512) {
        // ---- mask tile: lane = o (ballot dim), warp+k = i ; 4 chains/thread
        const uint32_t m  = blockIdx.x - 512;       // 0..255
        const uint32_t ob = (m & 15u) * 32u;        // o-block
        const uint32_t ib = (m >> 4) * 32u;         // i-block
        const uint32_t l  = t & 31u;
        const uint32_t w  = (uint32_t)t >> 5;
        const uint32_t o  = ob + l;
        const uint32_t ow = ob >> 5;

        uint32_t iidx[4];
        bool s[4];
#pragma unroll
        for (int k = 0; k < 4; ++k) {
            iidx[k] = ib + w + 8u * k;
            uint32_t n = o * 512u + iidx[k];
            float2 wt = reinterpret_cast<const float2*>(pw)[n];
            s[k] = edge_selected(wt, n);
        }
#pragma unroll
        for (int k = 0; k < 4; ++k) {
            uint32_t word = __ballot_sync(0xFFFFFFFFu, s[k]);
            if (l == 0) g_selC[ow * 512u + iidx[k]] = word;   // column-major
        }
        return;
    }

    // ---- sort half: bitonic on 512 keys, 2 per thread in registers
    const int row = blockIdx.x;
    float2 xv = reinterpret_cast<const float2*>(x + row * IN_DIM)[t];
    s_xv[2*t]   = xv.x;                        // exact values for final emit
    s_xv[2*t+1] = xv.y;
    // key = (valbits>>7)<<9 | idx  (monotone in value, 128-ulp ties)
    uint32_t a = ((__float_as_uint(xv.x) >> 7) << 9) | (uint32_t)(2*t);
    uint32_t b = ((__float_as_uint(xv.y) >> 7) << 9) | (uint32_t)(2*t+1);

    STAGE_J1(2)
    STAGE_SHFL(2,4)  STAGE_J1(4)
    STAGE_SHFL(4,8)  STAGE_SHFL(2,8)  STAGE_J1(8)
    STAGE_SHFL(8,16) STAGE_SHFL(4,16) STAGE_SHFL(2,16) STAGE_J1(16)
    STAGE_SHFL(16,32) STAGE_SHFL(8,32) STAGE_SHFL(4,32) STAGE_SHFL(2,32) STAGE_J1(32)
    STAGE_SHFL(32,64) STAGE_SHFL(16,64) STAGE_SHFL(8,64) STAGE_SHFL(4,64)
    STAGE_SHFL(2,64)  STAGE_J1(64)
    STAGE_SMEM(64,128)  TAIL32(128)
    STAGE_SMEM(128,256) STAGE_SMEM(64,256) TAIL32(256)
    STAGE_SMEM(256,512) STAGE_SMEM(128,512) STAGE_SMEM(64,512) TAIL32(512)

    if (t < 32) {                      // threads 0..31 hold sorted elems 0..63
        uint32_t ia = a & 511u, ib2 = b & 511u;
        g_top[row * 64 + 2*t]     = make_uint2(ia, __float_as_uint(s_xv[ia]));
        g_top[row * 64 + 2*t + 1] = make_uint2(ib2, __float_as_uint(s_xv[ib2]));
    }
}

// ---------------- 2) gather: one WARP per (b, o-word) -----------------------
// lane l probes candidate l for 32 o's at once; 5-step butterfly transposes
// the 32x32 hit matrix so lane o gets first-hit via ffs. ~30 ALU ops total.
#define TSTEP(V, K, M) {                                                      \
    uint32_t y_ = __shfl_xor_sync(0xFFFFFFFFu, V, K);                         \
    V = (lane & (K)) ? ((V & (M)) | ((y_ >> (K)) & ~(M)))                     \
                     : ((V & ~(M)) | ((y_ << (K)) & (M))); }

#define TRANSPOSE32(V) TSTEP(V, 16, 0xFFFF0000u) TSTEP(V, 8, 0xFF00FF00u)     \
                       TSTEP(V, 4,  0xF0F0F0F0u) TSTEP(V, 2, 0xCCCCCCCCu)     \
                       TSTEP(V, 1,  0xAAAAAAAAu)

__global__ __launch_bounds__(512) void gather_kernel(
    const float* __restrict__ x, float* __restrict__ out) {
    const int b    = blockIdx.x;
    const uint32_t ow = (uint32_t)threadIdx.x >> 5;   // warp -> o-word
    const int lane = threadIdx.x & 31;

    // candidate lane: (idx, exact value)
    uint2 kv = g_top[b * 64 + lane];                  // coalesced
    uint32_t m = g_selC[ow * 512u + kv.x];            // scattered, L2-hot
    float val = __uint_as_float(kv.y);

    TRANSPOSE32(m)            // now: lane o, bit l = hit(candidate l, output o)

    bool ok = (m != 0);
    float res = __shfl_sync(0xFFFFFFFFu, val, ok ? (__ffs(m) - 1) : 0);

    if (!__all_sync(0xFFFFFFFFu, ok)) {               // P ~ 1.3e-3 per warp
        uint2 kv2 = g_top[b * 64 + 32 + lane];
        uint32_t m2 = g_selC[ow * 512u + kv2.x];
        float val2 = __uint_as_float(kv2.y);
        TRANSPOSE32(m2)
        float r2 = __shfl_sync(0xFFFFFFFFu, val2, m2 ? (__ffs(m2) - 1) : 0);
        if (!ok && m2) { res = r2; ok = true; }

        if (!ok) {                                    // P ~ 1e-9: exact dense
            float best = INFINITY, ball2 = INFINITY;
            const float* xr = x + b * IN_DIM;
            for (int i = 0; i < IN_DIM; ++i) {
                float v = xr[i];
                ball2 = fminf(ball2, v);
                if ((g_selC[ow * 512u + i] >> lane) & 1u) best = fminf(best, v);
            }
            res = isinf(best) ? ball2 + 1.0f : best;  // zero-selected: impossible
        }
    }

    out[b * OUT_DIM + ow * 32u + lane] = res;         // coalesced
}

// ---------------------------------------------------------------------------
extern "C" void kernel_launch(void* const* d_in, const int* in_sizes, int n_in,
                              void* d_out, int out_size) {
    const float* x  = (const float*)d_in[0];   // [512, 512]
    const float* pw = (const float*)d_in[1];   // [512, 512, 2]
    float* out      = (float*)d_out;           // [512, 512]

    prep_kernel<<<768, 256>>>(x, pw);
    gather_kernel<<<B_DIM, 512>>>(x, out);
}